// round 16
// baseline (speedup 1.0000x reference)
#include <cuda_runtime.h>
#include <cuda_bf16.h>
#include <cstdint>
#include <math.h>

#define SSZ 1024
#define HSZ 8
#define BHZ 64
#define MT  8192
typedef __nv_bfloat16 bf;

// ---------------- scratch (device globals) ----------------
__device__ __align__(16) bf    g_xc[3][(size_t)MT * 2048];      // acts (hi|lo)
__device__ __align__(16) bf    g_wc[4][(size_t)1024 * 2048];    // W^T (hi|lo): v,k,q,m
__device__ __align__(16) bf    g_wgc[2][(size_t)128 * 256];     // WgX^T, WgY^T (hi|lo)
__device__ __align__(16) bf    g_khc[(size_t)BHZ * SSZ * 256];
__device__ __align__(16) bf    g_qhc[(size_t)BHZ * SSZ * 256];
__device__ __align__(16) bf    g_kgc[(size_t)BHZ * SSZ * 256];
__device__ __align__(16) bf    g_qgc[(size_t)BHZ * SSZ * 256];
__device__ __align__(16) bf    g_vtc[(size_t)BHZ * 128 * 2048]; // v^T [bh][d][2S]
__device__ __align__(16) bf    g_ctxc[(size_t)MT * 2048];

// ---------------- helpers ----------------
__device__ __forceinline__ uint32_t smem_u32(const void* p) {
    uint32_t a;
    asm("{ .reg .u64 t; cvta.to.shared.u64 t, %1; cvt.u32.u64 %0, t; }" : "=r"(a) : "l"(p));
    return a;
}
__device__ __forceinline__ uint32_t sw128(uint32_t o) { return o ^ ((o >> 3) & 0x70); }
__device__ __forceinline__ void split_bf(float v, bf& hi, bf& lo) {
    hi = __float2bfloat16(v);
    lo = __float2bfloat16(v - __bfloat162float(hi));
}
__device__ __forceinline__ void cpa_tile(uint32_t sdst, const bf* src, long ld, int t) {
#pragma unroll
    for (int r = 0; r < 4; r++) {
        const int it = t + r * 256;
        const int row = it >> 3, seg = it & 7;
        const uint32_t d = sdst + sw128(row * 128 + seg * 16);
        const bf* p = src + (size_t)row * ld + seg * 8;
        asm volatile("cp.async.cg.shared.global [%0], [%1], 16;" :: "r"(d), "l"(p));
    }
}
#define CPA_COMMIT() asm volatile("cp.async.commit_group;" ::: "memory")
#define CPA_WAIT2()  asm volatile("cp.async.wait_group 2;" ::: "memory")
#define CPA_WAIT1()  asm volatile("cp.async.wait_group 1;" ::: "memory")
#define CPA_WAIT0()  asm volatile("cp.async.wait_group 0;" ::: "memory")

#define MMA_CHUNK(sA, sB, ACC)                                                           \
    {                                                                                    \
        _Pragma("unroll")                                                                \
        for (int ks = 0; ks < 4; ks++) {                                                 \
            const int kb = ks * 32;                                                      \
            uint32_t a[4][4], bfr[4][2];                                                 \
            _Pragma("unroll")                                                            \
            for (int mi = 0; mi < 4; mi++) {                                             \
                const uint32_t addr = (sA) + sw128((warp_m * 64 + mi * 16 + (lane & 15)) * 128 \
                                                   + kb + (lane >> 4) * 16);             \
                asm volatile("ldmatrix.sync.aligned.m8n8.x4.shared.b16 {%0,%1,%2,%3}, [%4];" \
                    : "=r"(a[mi][0]), "=r"(a[mi][1]), "=r"(a[mi][2]), "=r"(a[mi][3]) : "r"(addr)); \
            }                                                                            \
            _Pragma("unroll")                                                            \
            for (int jp = 0; jp < 2; jp++) {                                             \
                const uint32_t addr = (sB) + sw128((warp_n * 32 + jp * 16 + ((lane >> 4) & 1) * 8 \
                                                    + (lane & 7)) * 128                  \
                                                   + kb + ((lane >> 3) & 1) * 16);       \
                asm volatile("ldmatrix.sync.aligned.m8n8.x4.shared.b16 {%0,%1,%2,%3}, [%4];" \
                    : "=r"(bfr[jp * 2][0]), "=r"(bfr[jp * 2][1]),                        \
                      "=r"(bfr[jp * 2 + 1][0]), "=r"(bfr[jp * 2 + 1][1]) : "r"(addr));   \
            }                                                                            \
            _Pragma("unroll")                                                            \
            for (int mi = 0; mi < 4; mi++)                                               \
                _Pragma("unroll")                                                        \
                for (int nj = 0; nj < 4; nj++)                                           \
                    asm volatile(                                                        \
                        "mma.sync.aligned.m16n8k16.row.col.f32.bf16.bf16.f32 "           \
                        "{%0,%1,%2,%3}, {%4,%5,%6,%7}, {%8,%9}, {%0,%1,%2,%3};"          \
                        : "+f"(ACC[mi][nj][0]), "+f"(ACC[mi][nj][1]),                    \
                          "+f"(ACC[mi][nj][2]), "+f"(ACC[mi][nj][3])                     \
                        : "r"(a[mi][0]), "r"(a[mi][1]), "r"(a[mi][2]), "r"(a[mi][3]),    \
                          "r"(bfr[nj][0]), "r"(bfr[nj][1]));                             \
        }                                                                                \
    }

// ---------------- shared 3-pass split mainloop (A,B stored hi|lo) ----------------
__device__ __forceinline__ void gemm_main(
    const bf* Ab, const bf* Bb, long lda, long ldb, long loA, long loB, int nchp,
    uint32_t smbase, int t, int lane, int warp_m, int warp_n, float (&acc)[4][4][4])
{
    const int nch = nchp * 3;
#define ACHUNK(j) (Ab + ((j) >= 2 * nchp ? loA : 0) + (size_t)((j) % nchp) * 64)
#define BCHUNK(j) (Bb + (((j) >= nchp && (j) < 2 * nchp) ? loB : 0) + (size_t)((j) % nchp) * 64)
    cpa_tile(smbase,         ACHUNK(0), lda, t);
    cpa_tile(smbase + 16384, BCHUNK(0), ldb, t);
    CPA_COMMIT();
    if (nch > 1) {
        cpa_tile(smbase + 32768, ACHUNK(1), lda, t);
        cpa_tile(smbase + 49152, BCHUNK(1), ldb, t);
    }
    CPA_COMMIT();
    for (int i = 0; i < nch; i++) {
        CPA_WAIT1();
        __syncthreads();
        const uint32_t sA = smbase + (i & 1) * 32768;
        MMA_CHUNK(sA, sA + 16384, acc);
        __syncthreads();
        if (i + 2 < nch) {
            cpa_tile(smbase + (i & 1) * 32768,         ACHUNK(i + 2), lda, t);
            cpa_tile(smbase + (i & 1) * 32768 + 16384, BCHUNK(i + 2), ldb, t);
        }
        CPA_COMMIT();
    }
    CPA_WAIT0();
#undef ACHUNK
#undef BCHUNK
}

#define STAGE_ACC(ACC, SCALE0, SCALE1)                                                   \
    if (warp_n == cb) {                                                                  \
        _Pragma("unroll")                                                                \
        for (int mi = 0; mi < 4; mi++)                                                   \
            _Pragma("unroll")                                                            \
            for (int nj = 0; nj < 4; nj++) {                                             \
                const int r  = warp_m * 64 + mi * 16 + (lane >> 2);                      \
                const int cc = nj * 8 + (lane & 3) * 2;                                  \
                stg[r * 33 + cc]           = ACC[mi][nj][0] * (SCALE0);                  \
                stg[r * 33 + cc + 1]       = ACC[mi][nj][1] * (SCALE0);                  \
                stg[(r + 8) * 33 + cc]     = ACC[mi][nj][2] * (SCALE1);                  \
                stg[(r + 8) * 33 + cc + 1] = ACC[mi][nj][3] * (SCALE1);                  \
            }                                                                            \
    }

// ---------------- merged QKV projection: grid (64, 8, 3) ----------------
struct PArgs {
    const bf *A0, *A1, *A2, *B0, *B1, *B2;
    const float *b0, *b1, *b2;
    bf *o0, *o1, *o2;
};

__global__ __launch_bounds__(256) void tc_projVKQ(PArgs g)
{
    extern __shared__ __align__(16) char smt[];
    const uint32_t smbase = smem_u32(smt);
    const int t = threadIdx.x, lane = t & 31, wid = t >> 5;
    const int warp_m = wid >> 2, warp_n = wid & 3;
    const int m0 = blockIdx.x * 128, n0 = blockIdx.y * 128;
    const int z = blockIdx.z;

    const bf* A = (z == 0 ? g.A0 : z == 1 ? g.A1 : g.A2) + (size_t)m0 * 2048;
    const bf* B = (z == 0 ? g.B0 : z == 1 ? g.B1 : g.B2) + (size_t)n0 * 2048;
    const float* bias = z == 0 ? g.b0 : z == 1 ? g.b1 : g.b2;
    bf* oc = z == 0 ? g.o0 : z == 1 ? g.o1 : g.o2;

    float acc[4][4][4];
#pragma unroll
    for (int i = 0; i < 4; i++)
#pragma unroll
        for (int j = 0; j < 4; j++)
#pragma unroll
            for (int c = 0; c < 4; c++) acc[i][j][c] = 0.f;

    gemm_main(A, B, 2048, 2048, 1024, 1024, 16, smbase, t, lane, warp_m, warp_n, acc);

    float* stg = (float*)smt;
    for (int cb = 0; cb < 4; cb++) {
        __syncthreads();
        STAGE_ACC(acc, 1.f, 1.f);
        __syncthreads();
        if (z == 0) {
            const int dloc = t & 31, soff = (t >> 5) * 16;
            const int b = m0 >> 10, h = blockIdx.y, d = cb * 32 + dloc;
            const int scol = (m0 & 1023) + soff;
            bf hi16[16], lo16[16];
#pragma unroll
            for (int i2 = 0; i2 < 16; i2++) {
                float v = stg[(soff + i2) * 33 + dloc] + bias[n0 + d];
                split_bf(v, hi16[i2], lo16[i2]);
            }
            bf* dst = oc + ((size_t)(b * HSZ + h) * 128 + d) * 2048 + scol;
            uint4* hv = (uint4*)hi16; uint4* lv = (uint4*)lo16;
            *(uint4*)(dst) = hv[0];          *(uint4*)(dst + 8) = hv[1];
            *(uint4*)(dst + 1024) = lv[0];   *(uint4*)(dst + 1032) = lv[1];
        } else {
            const int row = t >> 1, c0 = (t & 1) * 16;
            const float* sr = stg + row * 33 + c0;
            const int h = blockIdx.y, m = m0 + row, b = m >> 10, s = m & 1023;
            const int d0 = cb * 32 + c0;
            bf* cd = oc + ((size_t)(b * HSZ + h) * SSZ + s) * 256 + d0;
            bf hi16[16], lo16[16];
#pragma unroll
            for (int c = 0; c < 16; c++)
                split_bf(sr[c] + bias[n0 + d0 + c], hi16[c], lo16[c]);
            uint4* hv = (uint4*)hi16; uint4* lv = (uint4*)lo16;
            *(uint4*)(cd) = hv[0];        *(uint4*)(cd + 8) = hv[1];
            *(uint4*)(cd + 128) = lv[0];  *(uint4*)(cd + 136) = lv[1];
        }
    }
}

// ---------------- fused gate: GEMMs + row-dot + sigmoid + apply. grid (512) ----------------
__global__ __launch_bounds__(256) void tc_gatefused(
    const bf* __restrict__ wg0, const bf* __restrict__ wg1,
    const float* __restrict__ bgX, const float* __restrict__ bgY,
    const float* __restrict__ Wg2, const float* __restrict__ bg2)
{
    extern __shared__ __align__(16) char smt[];
    const uint32_t smbase = smem_u32(smt);
    const int t = threadIdx.x, lane = t & 31, wid = t >> 5;
    const int warp_m = wid >> 2, warp_n = wid & 3;
    const int m0 = blockIdx.x * 128;          // row block in flattened (bh*S)

    const bf* Ak = g_khc + (size_t)m0 * 256;
    const bf* Aq = g_qhc + (size_t)m0 * 256;

    float acc0[4][4][4], acc1[4][4][4];
#pragma unroll
    for (int i = 0; i < 4; i++)
#pragma unroll
        for (int j = 0; j < 4; j++)
#pragma unroll
            for (int c = 0; c < 4; c++) { acc0[i][j][c] = 0.f; acc1[i][j][c] = 0.f; }

    gemm_main(Ak, wg0, 256, 256, 128, 128, 2, smbase, t, lane, warp_m, warp_n, acc0);
    gemm_main(Aq, wg1, 256, 256, 128, 128, 2, smbase, t, lane, warp_m, warp_n, acc1);

    // per-row dot with Wg2 across 4 col-blocks
    float* stg  = (float*)smt;                 // gx staging 128x33
    float* stg1 = stg + 128 * 33;              // gy staging 128x33
    float* sred = stg1 + 128 * 33;             // 2x256 partials
    float* gk_arr = sred + 512;                // 128 gates
    float* gq_arr = gk_arr + 128;

    const int row = t >> 1, c0 = (t & 1) * 16;
    float s0 = 0.f, s1 = 0.f;
    for (int cb = 0; cb < 4; cb++) {
        __syncthreads();
        STAGE_ACC(acc0, 1.f, 1.f);
        {
            float* stg_sv = stg; float* stg_ = stg1;
            float* stg2 = stg_; (void)stg_sv;
            // stage acc1 into stg1
            if (warp_n == cb) {
#pragma unroll
                for (int mi = 0; mi < 4; mi++)
#pragma unroll
                    for (int nj = 0; nj < 4; nj++) {
                        const int r  = warp_m * 64 + mi * 16 + (lane >> 2);
                        const int cc = nj * 8 + (lane & 3) * 2;
                        stg2[r * 33 + cc]           = acc1[mi][nj][0];
                        stg2[r * 33 + cc + 1]       = acc1[mi][nj][1];
                        stg2[(r + 8) * 33 + cc]     = acc1[mi][nj][2];
                        stg2[(r + 8) * 33 + cc + 1] = acc1[mi][nj][3];
                    }
            }
        }
        __syncthreads();
        const int d0 = cb * 32 + c0;
#pragma unroll
        for (int c = 0; c < 16; c++) {
            const float gx = stg[row * 33 + c0 + c]  + bgX[d0 + c];
            const float gy = stg1[row * 33 + c0 + c] + bgY[d0 + c];
            const float tv = gx * gy;
            s0 = fmaf(tv, Wg2[(d0 + c) * 2],     s0);
            s1 = fmaf(tv, Wg2[(d0 + c) * 2 + 1], s1);
        }
    }
    sred[t] = s0; sred[256 + t] = s1;
    __syncthreads();
    if ((t & 1) == 0) {
        const float tot0 = sred[t] + sred[t + 1];
        const float tot1 = sred[256 + t] + sred[256 + t + 1];
        gk_arr[row] = 1.f / (1.f + __expf(-(tot0 + bg2[0])));
        gq_arr[row] = 1.f / (1.f + __expf(-(tot1 + bg2[1])));
    }
    __syncthreads();

    // apply gates: reconstruct hi+lo, scale, re-split, write kgc/qgc
    for (int idx = t; idx < 128 * 64; idx += 256) {
        const int r = idx >> 6, dp = (idx & 63) * 2;
        const size_t base = ((size_t)m0 + r) * 256 + dp;
        const float gk = gk_arr[r], gq = gq_arr[r];
        __nv_bfloat162 h2, l2;
        h2 = *(const __nv_bfloat162*)(g_khc + base);
        l2 = *(const __nv_bfloat162*)(g_khc + base + 128);
        float k0 = (__bfloat162float(h2.x) + __bfloat162float(l2.x)) * gk;
        float k1 = (__bfloat162float(h2.y) + __bfloat162float(l2.y)) * gk;
        bf hh, ll; __nv_bfloat162 oh, ol;
        split_bf(k0, hh, ll); oh.x = hh; ol.x = ll;
        split_bf(k1, hh, ll); oh.y = hh; ol.y = ll;
        *(__nv_bfloat162*)(g_kgc + base) = oh;
        *(__nv_bfloat162*)(g_kgc + base + 128) = ol;
        h2 = *(const __nv_bfloat162*)(g_qhc + base);
        l2 = *(const __nv_bfloat162*)(g_qhc + base + 128);
        float q0 = (__bfloat162float(h2.x) + __bfloat162float(l2.x)) * gq;
        float q1 = (__bfloat162float(h2.y) + __bfloat162float(l2.y)) * gq;
        split_bf(q0, hh, ll); oh.x = hh; ol.x = ll;
        split_bf(q1, hh, ll); oh.y = hh; ol.y = ll;
        *(__nv_bfloat162*)(g_qgc + base) = oh;
        *(__nv_bfloat162*)(g_qgc + base + 128) = ol;
    }
}

// ---------------- final projection: grid (64, 8) ----------------
__global__ __launch_bounds__(256) void tc_final(
    const bf* __restrict__ A, const bf* __restrict__ B,
    const float* __restrict__ bias, float* __restrict__ of)
{
    extern __shared__ __align__(16) char smt[];
    const uint32_t smbase = smem_u32(smt);
    const int t = threadIdx.x, lane = t & 31, wid = t >> 5;
    const int warp_m = wid >> 2, warp_n = wid & 3;
    const int m0 = blockIdx.x * 128, n0 = blockIdx.y * 128;

    float acc[4][4][4];
#pragma unroll
    for (int i = 0; i < 4; i++)
#pragma unroll
        for (int j = 0; j < 4; j++)
#pragma unroll
            for (int c = 0; c < 4; c++) acc[i][j][c] = 0.f;

    gemm_main(A + (size_t)m0 * 2048, B + (size_t)n0 * 2048,
              2048, 2048, 1024, 1024, 16, smbase, t, lane, warp_m, warp_n, acc);

    float* stg = (float*)smt;
    for (int cb = 0; cb < 4; cb++) {
        __syncthreads();
        STAGE_ACC(acc, 1.f, 1.f);
        __syncthreads();
        const int row = t >> 1, c0 = (t & 1) * 16;
        const float* sr = stg + row * 33 + c0;
        const int nt = n0 + cb * 32 + c0;
        float* fd = of + (size_t)(m0 + row) * 1024 + nt;
#pragma unroll
        for (int c = 0; c < 16; c += 4) {
            float4 w;
            w.x = sr[c]     + bias[nt + c];
            w.y = sr[c + 1] + bias[nt + c + 1];
            w.z = sr[c + 2] + bias[nt + c + 2];
            w.w = sr[c + 3] + bias[nt + c + 3];
            *(float4*)(fd + c) = w;
        }
    }
}

// ---------------- fused flash attention v3 (unchanged) ----------------
#define FQB  0
#define FPB  65536
#define FSB  131072
#define FSM_PMAX 180224
#define FSM_PSUM (180224 + 2048)
#define FSM_MRUN (180224 + 4096)
#define FSM_LRUN (180224 + 4608)
#define FSM_MASK (180224 + 5120)
#define FSMEM    (180224 + 5376)

__global__ __launch_bounds__(256) void flash_att(
    const bf* __restrict__ qg, const bf* __restrict__ kg, const bf* __restrict__ vt,
    const unsigned char* __restrict__ mask, bf* __restrict__ ctx)
{
    extern __shared__ __align__(16) char smt[];
    const uint32_t smbase = smem_u32(smt);
    float* pmax = (float*)(smt + FSM_PMAX);
    float* psum = (float*)(smt + FSM_PSUM);
    float* m_run = (float*)(smt + FSM_MRUN);
    float* l_run = (float*)(smt + FSM_LRUN);
    unsigned char* mk = (unsigned char*)(smt + FSM_MASK);

    const int t = threadIdx.x, lane = t & 31, wid = t >> 5;
    const int warp_m = wid >> 2, warp_n = wid & 3;
    const int m0 = blockIdx.x * 128;
    const int bh = blockIdx.z, b = bh >> 3, h = bh & 7;

    const bf* Aq = qg + (size_t)bh * SSZ * 256 + (size_t)m0 * 256;
    const bf* Bk = kg + (size_t)bh * SSZ * 256;
    const bf* Vt = vt + (size_t)bh * 128 * 2048;

#pragma unroll
    for (int c = 0; c < 4; c++)
        cpa_tile(smbase + FQB + c * 16384, Aq + c * 64, 256, t);
    CPA_COMMIT();

    float oacc[4][4][4];
#pragma unroll
    for (int i = 0; i < 4; i++)
#pragma unroll
        for (int j = 0; j < 4; j++)
#pragma unroll
            for (int c = 0; c < 4; c++) oacc[i][j][c] = 0.f;

    if (t < 128) { m_run[t] = -1e30f; l_run[t] = 0.f; }
    CPA_WAIT0();
    __syncthreads();

    for (int kt = 0; kt < 8; kt++) {
        if (t < 128) mk[t] = mask[b * SSZ + kt * 128 + t];
        const bf* Bb = Bk + (size_t)(kt * 128) * 256;

        float sacc[4][4][4];
#pragma unroll
        for (int i = 0; i < 4; i++)
#pragma unroll
            for (int j = 0; j < 4; j++)
#pragma unroll
                for (int c = 0; c < 4; c++) sacc[i][j][c] = 0.f;

        cpa_tile(smbase + FSB,         Bb,       256, t); CPA_COMMIT();
        cpa_tile(smbase + FSB + 16384, Bb + 64,  256, t); CPA_COMMIT();
        cpa_tile(smbase + FSB + 32768, Bb + 128, 256, t); CPA_COMMIT();
        CPA_WAIT2(); __syncthreads();
        MMA_CHUNK(smbase + FQB,         smbase + FSB, sacc);
        MMA_CHUNK(smbase + FQB + 32768, smbase + FSB, sacc);
        __syncthreads();
        cpa_tile(smbase + FSB, Bb + 192, 256, t); CPA_COMMIT();
        CPA_WAIT2(); __syncthreads();
        MMA_CHUNK(smbase + FQB + 16384, smbase + FSB + 16384, sacc);
        MMA_CHUNK(smbase + FQB + 49152, smbase + FSB + 16384, sacc);
        CPA_WAIT1(); __syncthreads();
        MMA_CHUNK(smbase + FQB,         smbase + FSB + 32768, sacc);
        CPA_WAIT0(); __syncthreads();
        MMA_CHUNK(smbase + FQB + 16384, smbase + FSB, sacc);
        __syncthreads();

        const float scl = 0.08838834764831845f;
#pragma unroll
        for (int mi = 0; mi < 4; mi++)
#pragma unroll
            for (int nj = 0; nj < 4; nj++) {
                const int cbase = warp_n * 32 + nj * 8 + (lane & 3) * 2;
                const bool mk0 = mk[cbase] != 0, mk1 = mk[cbase + 1] != 0;
                sacc[mi][nj][0] = mk0 ? -1e9f : sacc[mi][nj][0] * scl;
                sacc[mi][nj][1] = mk1 ? -1e9f : sacc[mi][nj][1] * scl;
                sacc[mi][nj][2] = mk0 ? -1e9f : sacc[mi][nj][2] * scl;
                sacc[mi][nj][3] = mk1 ? -1e9f : sacc[mi][nj][3] * scl;
            }

#pragma unroll
        for (int mi = 0; mi < 4; mi++) {
            float mx0 = -1e30f, mx1 = -1e30f;
#pragma unroll
            for (int nj = 0; nj < 4; nj++) {
                mx0 = fmaxf(mx0, fmaxf(sacc[mi][nj][0], sacc[mi][nj][1]));
                mx1 = fmaxf(mx1, fmaxf(sacc[mi][nj][2], sacc[mi][nj][3]));
            }
            mx0 = fmaxf(mx0, __shfl_xor_sync(0xFFFFFFFFu, mx0, 1));
            mx0 = fmaxf(mx0, __shfl_xor_sync(0xFFFFFFFFu, mx0, 2));
            mx1 = fmaxf(mx1, __shfl_xor_sync(0xFFFFFFFFu, mx1, 1));
            mx1 = fmaxf(mx1, __shfl_xor_sync(0xFFFFFFFFu, mx1, 2));
            if ((lane & 3) == 0) {
                const int r = warp_m * 64 + mi * 16 + (lane >> 2);
                pmax[warp_n * 128 + r] = mx0;
                pmax[warp_n * 128 + r + 8] = mx1;
            }
        }
        __syncthreads();

        cpa_tile(smbase + FSB,          Vt + (size_t)kt * 128,        2048, t); CPA_COMMIT();
        cpa_tile(smbase + FSB + 16384,  Vt + (size_t)kt * 128 + 64,   2048, t); CPA_COMMIT();
        cpa_tile(smbase + FSB + 32768,  Vt + 1024 + (size_t)kt * 128, 2048, t); CPA_COMMIT();

#pragma unroll
        for (int mi = 0; mi < 4; mi++) {
            const int r0 = warp_m * 64 + mi * 16 + (lane >> 2), r1 = r0 + 8;
            const float mo0 = m_run[r0], mo1 = m_run[r1];
            float mn0 = fmaxf(fmaxf(pmax[r0], pmax[128 + r0]), fmaxf(pmax[256 + r0], pmax[384 + r0]));
            float mn1 = fmaxf(fmaxf(pmax[r1], pmax[128 + r1]), fmaxf(pmax[256 + r1], pmax[384 + r1]));
            mn0 = fmaxf(mn0, mo0); mn1 = fmaxf(mn1, mo1);
            const float f0 = __expf(mo0 - mn0), f1 = __expf(mo1 - mn1);
            float s0 = 0.f, s1 = 0.f;
#pragma unroll
            for (int nj = 0; nj < 4; nj++) {
                sacc[mi][nj][0] = __expf(sacc[mi][nj][0] - mn0); s0 += sacc[mi][nj][0];
                sacc[mi][nj][1] = __expf(sacc[mi][nj][1] - mn0); s0 += sacc[mi][nj][1];
                sacc[mi][nj][2] = __expf(sacc[mi][nj][2] - mn1); s1 += sacc[mi][nj][2];
                sacc[mi][nj][3] = __expf(sacc[mi][nj][3] - mn1); s1 += sacc[mi][nj][3];
                oacc[mi][nj][0] *= f0; oacc[mi][nj][1] *= f0;
                oacc[mi][nj][2] *= f1; oacc[mi][nj][3] *= f1;
            }
            s0 += __shfl_xor_sync(0xFFFFFFFFu, s0, 1); s0 += __shfl_xor_sync(0xFFFFFFFFu, s0, 2);
            s1 += __shfl_xor_sync(0xFFFFFFFFu, s1, 1); s1 += __shfl_xor_sync(0xFFFFFFFFu, s1, 2);
            if ((lane & 3) == 0) {
                psum[warp_n * 128 + r0] = s0;
                psum[warp_n * 128 + r1] = s1;
            }
        }
        __syncthreads();
        if (t < 128) {
            const float mo = m_run[t];
            float mn = fmaxf(fmaxf(pmax[t], pmax[128 + t]), fmaxf(pmax[256 + t], pmax[384 + t]));
            mn = fmaxf(mn, mo);
            l_run[t] = l_run[t] * __expf(mo - mn)
                     + psum[t] + psum[128 + t] + psum[256 + t] + psum[384 + t];
            m_run[t] = mn;
        }

        {
            const int hc = warp_n >> 1;
            char* pbh = smt + FPB + hc * 16384;
            char* pbl = smt + FPB + 32768 + hc * 16384;
#pragma unroll
            for (int mi = 0; mi < 4; mi++)
#pragma unroll
                for (int nj = 0; nj < 4; nj++) {
                    const int r0 = warp_m * 64 + mi * 16 + (lane >> 2);
                    const int lc = (warp_n & 1) * 32 + nj * 8 + (lane & 3) * 2;
                    __nv_bfloat162 h0, h1, l0v, l1v;
                    bf hh, ll;
                    split_bf(sacc[mi][nj][0], hh, ll); h0.x = hh; l0v.x = ll;
                    split_bf(sacc[mi][nj][1], hh, ll); h0.y = hh; l0v.y = ll;
                    split_bf(sacc[mi][nj][2], hh, ll); h1.x = hh; l1v.x = ll;
                    split_bf(sacc[mi][nj][3], hh, ll); h1.y = hh; l1v.y = ll;
                    *(__nv_bfloat162*)(pbh + sw128(r0 * 128 + lc * 2)) = h0;
                    *(__nv_bfloat162*)(pbh + sw128((r0 + 8) * 128 + lc * 2)) = h1;
                    *(__nv_bfloat162*)(pbl + sw128(r0 * 128 + lc * 2)) = l0v;
                    *(__nv_bfloat162*)(pbl + sw128((r0 + 8) * 128 + lc * 2)) = l1v;
                }
        }
        __syncthreads();

        CPA_WAIT2(); __syncthreads();
        MMA_CHUNK(smbase + FPB,          smbase + FSB, oacc);
        MMA_CHUNK(smbase + FPB + 32768,  smbase + FSB, oacc);
        __syncthreads();
        cpa_tile(smbase + FSB, Vt + 1024 + (size_t)kt * 128 + 64, 2048, t);
        CPA_COMMIT();
        CPA_WAIT2(); __syncthreads();
        MMA_CHUNK(smbase + FPB + 16384,  smbase + FSB + 16384, oacc);
        MMA_CHUNK(smbase + FPB + 49152,  smbase + FSB + 16384, oacc);
        CPA_WAIT1(); __syncthreads();
        MMA_CHUNK(smbase + FPB,          smbase + FSB + 32768, oacc);
        CPA_WAIT0(); __syncthreads();
        MMA_CHUNK(smbase + FPB + 16384,  smbase + FSB, oacc);
        __syncthreads();
    }

    float inv0[4], inv1[4];
#pragma unroll
    for (int mi = 0; mi < 4; mi++) {
        const int r0 = warp_m * 64 + mi * 16 + (lane >> 2);
        inv0[mi] = 1.f / l_run[r0];
        inv1[mi] = 1.f / l_run[r0 + 8];
    }
    float* stg = (float*)smt;
    for (int cb = 0; cb < 4; cb++) {
        __syncthreads();
        STAGE_ACC(oacc, inv0[mi], inv1[mi]);
        __syncthreads();
        const int row = t >> 1, c0 = (t & 1) * 16;
        const float* sr = stg + row * 33 + c0;
        const int n = cb * 32 + c0;
        bf* cd = ctx + ((size_t)b * SSZ + m0 + row) * 2048 + h * 128 + n;
        bf hi16[16], lo16[16];
#pragma unroll
        for (int c = 0; c < 16; c++) split_bf(sr[c], hi16[c], lo16[c]);
        uint4* hv = (uint4*)hi16; uint4* lv = (uint4*)lo16;
        *(uint4*)(cd) = hv[0];          *(uint4*)(cd + 8) = hv[1];
        *(uint4*)(cd + 1024) = lv[0];   *(uint4*)(cd + 1032) = lv[1];
    }
}

// ---------------- prep kernels ----------------
__global__ __launch_bounds__(256) void split_act(const float* v, const float* k, const float* q)
{
    const float* s = blockIdx.z == 0 ? v : blockIdx.z == 1 ? k : q;
    bf* dst = g_xc[blockIdx.z];
    const size_t i = ((size_t)blockIdx.x * 256 + threadIdx.x) * 4;
    const size_t row = i >> 10, col = i & 1023;
    float4 x = *(const float4*)(s + i);
    bf h[4], l[4];
    split_bf(x.x, h[0], l[0]); split_bf(x.y, h[1], l[1]);
    split_bf(x.z, h[2], l[2]); split_bf(x.w, h[3], l[3]);
    bf* d = dst + row * 2048 + col;
    *(uint2*)(d) = *(uint2*)h;
    *(uint2*)(d + 1024) = *(uint2*)l;
}

__global__ void wsplit(const float* W, bf* Wc, int K, int N)
{
    __shared__ float sm[32][33];
    const int k0 = blockIdx.y * 32, n0 = blockIdx.x * 32;
    for (int r = threadIdx.y; r < 32; r += 8)
        sm[r][threadIdx.x] = W[(size_t)(k0 + r) * N + n0 + threadIdx.x];
    __syncthreads();
    for (int r = threadIdx.y; r < 32; r += 8) {
        bf hi, lo; split_bf(sm[threadIdx.x][r], hi, lo);
        bf* d = Wc + (size_t)(n0 + r) * 2 * K + k0 + threadIdx.x;
        d[0] = hi; d[K] = lo;
    }
}

// ---------------- launch ----------------
#define TCSMEM 65536

extern "C" void kernel_launch(void* const* d_in, const int* in_sizes, int n_in,
                              void* d_out, int out_size)
{
    (void)in_sizes; (void)n_in; (void)out_size;
    const float* v  = (const float*)d_in[0];
    const float* k  = (const float*)d_in[1];
    const float* q  = (const float*)d_in[2];
    const unsigned char* mask = (const unsigned char*)d_in[3];
    const float* Wv = (const float*)d_in[4];  const float* bv = (const float*)d_in[5];
    const float* Wk = (const float*)d_in[6];  const float* bk = (const float*)d_in[7];
    const float* Wq = (const float*)d_in[8];  const float* bq = (const float*)d_in[9];
    const float* Wm = (const float*)d_in[10]; const float* bm = (const float*)d_in[11];
    const float* WgX = (const float*)d_in[12]; const float* bgX = (const float*)d_in[13];
    const float* WgY = (const float*)d_in[14]; const float* bgY = (const float*)d_in[15];
    const float* Wg2 = (const float*)d_in[16]; const float* bg2 = (const float*)d_in[17];
    float* outp = (float*)d_out;

    cudaFuncSetAttribute(tc_projVKQ,  cudaFuncAttributeMaxDynamicSharedMemorySize, TCSMEM);
    cudaFuncSetAttribute(tc_gatefused, cudaFuncAttributeMaxDynamicSharedMemorySize, TCSMEM);
    cudaFuncSetAttribute(tc_final,    cudaFuncAttributeMaxDynamicSharedMemorySize, TCSMEM);
    cudaFuncSetAttribute(flash_att,   cudaFuncAttributeMaxDynamicSharedMemorySize, FSMEM);

    bf* wc0; bf* wc1; bf* wc2; bf* wc3; bf* wg0; bf* wg1;
    bf* xc0; bf* xc1; bf* xc2;
    cudaGetSymbolAddress((void**)&wc0, g_wc);  wc1 = wc0 + (size_t)1024 * 2048;
    wc2 = wc1 + (size_t)1024 * 2048; wc3 = wc2 + (size_t)1024 * 2048;
    cudaGetSymbolAddress((void**)&wg0, g_wgc); wg1 = wg0 + (size_t)128 * 256;
    cudaGetSymbolAddress((void**)&xc0, g_xc);  xc1 = xc0 + (size_t)MT * 2048; xc2 = xc1 + (size_t)MT * 2048;
    bf *khc, *qhc, *kgc, *qgc, *vtc, *ctxc;
    cudaGetSymbolAddress((void**)&khc, g_khc); cudaGetSymbolAddress((void**)&qhc, g_qhc);
    cudaGetSymbolAddress((void**)&kgc, g_kgc); cudaGetSymbolAddress((void**)&qgc, g_qgc);
    cudaGetSymbolAddress((void**)&vtc, g_vtc); cudaGetSymbolAddress((void**)&ctxc, g_ctxc);

    split_act<<<dim3(8192, 1, 3), 256>>>(v, k, q);
    wsplit<<<dim3(32, 32), dim3(32, 8)>>>(Wv, wc0, 1024, 1024);
    wsplit<<<dim3(32, 32), dim3(32, 8)>>>(Wk, wc1, 1024, 1024);
    wsplit<<<dim3(32, 32), dim3(32, 8)>>>(Wq, wc2, 1024, 1024);
    wsplit<<<dim3(32, 32), dim3(32, 8)>>>(Wm, wc3, 1024, 1024);
    wsplit<<<dim3(4, 4),   dim3(32, 8)>>>(WgX, wg0, 128, 128);
    wsplit<<<dim3(4, 4),   dim3(32, 8)>>>(WgY, wg1, 128, 128);

    PArgs p = {};
    p.A0 = xc0; p.A1 = xc1; p.A2 = xc2;
    p.B0 = wc0; p.B1 = wc1; p.B2 = wc2;
    p.b0 = bv;  p.b1 = bk;  p.b2 = bq;
    p.o0 = vtc; p.o1 = khc; p.o2 = qhc;
    tc_projVKQ<<<dim3(64, 8, 3), 256, TCSMEM>>>(p);

    tc_gatefused<<<512, 256, TCSMEM>>>(wg0, wg1, bgX, bgY, Wg2, bg2);

    flash_att<<<dim3(8, 1, BHZ), 256, FSMEM>>>(qgc, kgc, vtc, mask, ctxc);

    tc_final<<<dim3(64, 8), 256, TCSMEM>>>(ctxc, wc3, bm, outp);
}